// round 14
// baseline (speedup 1.0000x reference)
#include <cuda_runtime.h>
#include <cstdint>

// Problem constants
#define N_ 64
#define L_ 512
#define T_ 128
#define D_ 1024
#define D4 (D_ / 4)          // 256 float4 per row
#define NPAIRS 4             // warp-pairs per CTA (8 warps, 256 threads)
#define ROWS_PER_PAIR 8
#define TILE_ROWS (NPAIRS * ROWS_PER_PAIR)    // 32
#define NTILES (L_ / TILE_ROWS)               // 16

// Scratch (allocation-free device globals; zero-initialized at load, and
// pass2 restores them to zero each launch -> no zero kernel needed).
__device__ float g_e[N_][L_];       // unnormalized exp(scores) (overwritten)
__device__ float g_g[N_][D_];       // atomically accumulated weighted sums
__device__ float g_z4[N_][4];       // 4 replicas of sum-of-exps (one per pass2 CTA)

// ---------------------------------------------------------------------------
// Pass 1: ONE DRAM read of f1. Two-warp teams: each warp holds a HALF row
// (x[4], acc[4]). Partial dots exchanged via double-buffered smem + 1 barrier
// per row. e = exp(dot): no max-shift needed (scores are O(1)); exp-weighted
// partials are associative -> REDG combine into g_g / g_z4.
// Grid (NTILES=16, N=64) = 1024 CTAs x 256 threads.
// ---------------------------------------------------------------------------
__global__ void __launch_bounds__(256) pass1_kernel(
    const float* __restrict__ f1, const float* __restrict__ w)
{
    __shared__ float4 wsh[D4];                   // 4 KB
    __shared__ float4 accsh[NPAIRS][D4];         // 16 KB
    __shared__ float  sdot[2][8];                // double-buffered partial dots
    __shared__ float  zsh[NPAIRS];

    int tid = threadIdx.x, lane = tid & 31, warp = tid >> 5;
    int pair = warp >> 1, h = warp & 1;          // h: which half of the row
    wsh[tid] = reinterpret_cast<const float4*>(w)[tid];
    __syncthreads();

    int tile = blockIdx.x, n = blockIdx.y;
    int row0 = tile * TILE_ROWS + pair * ROWS_PER_PAIR;
    const float4* base = reinterpret_cast<const float4*>(f1)
                         + ((size_t)n * L_ + row0) * D4 + h * (D4 / 2);

    float4 acc[4];
#pragma unroll
    for (int j = 0; j < 4; ++j) acc[j] = make_float4(0.f, 0.f, 0.f, 0.f);
    float zacc = 0.f;

#pragma unroll 1
    for (int r = 0; r < ROWS_PER_PAIR; ++r) {
        const float4* p = base + (size_t)r * D4;
        float4 x[4];
#pragma unroll
        for (int j = 0; j < 4; ++j) x[j] = p[lane + 32 * j];

        float d = 0.f;
#pragma unroll
        for (int j = 0; j < 4; ++j) {
            float4 ww = wsh[h * (D4 / 2) + lane + 32 * j];
            d += x[j].x * ww.x + x[j].y * ww.y + x[j].z * ww.z + x[j].w * ww.w;
        }
#pragma unroll
        for (int o = 16; o > 0; o >>= 1)
            d += __shfl_xor_sync(0xffffffffu, d, o);
        if (lane == 0) sdot[r & 1][warp] = d;
        __syncthreads();

        float e = __expf(sdot[r & 1][pair * 2] + sdot[r & 1][pair * 2 + 1]);
        if (h == 0) {
            zacc += e;
            if (lane == 0) g_e[n][row0 + r] = e;
        }
#pragma unroll
        for (int j = 0; j < 4; ++j) {
            acc[j].x = fmaf(e, x[j].x, acc[j].x);
            acc[j].y = fmaf(e, x[j].y, acc[j].y);
            acc[j].z = fmaf(e, x[j].z, acc[j].z);
            acc[j].w = fmaf(e, x[j].w, acc[j].w);
        }
    }

#pragma unroll
    for (int j = 0; j < 4; ++j)
        accsh[pair][h * (D4 / 2) + lane + 32 * j] = acc[j];
    if (h == 0 && lane == 0) zsh[pair] = zacc;
    __syncthreads();

    // cross-pair reduce then REDG into global accumulators
    float4 t = accsh[0][tid];
#pragma unroll
    for (int k = 1; k < NPAIRS; ++k) {
        float4 a = accsh[k][tid];
        t.x += a.x; t.y += a.y; t.z += a.z; t.w += a.w;
    }
    float* gcol = &g_g[n][tid * 4];
    atomicAdd(gcol + 0, t.x);
    atomicAdd(gcol + 1, t.y);
    atomicAdd(gcol + 2, t.z);
    atomicAdd(gcol + 3, t.w);
    if (tid < 4)   // 4 z-replicas, one per future pass2 CTA
        atomicAdd(&g_z4[n][tid], (zsh[0] + zsh[1]) + (zsh[2] + zsh[3]));
}

// ---------------------------------------------------------------------------
// Pass 2: pure broadcast + self-clean. Grid (N=64, 4) x 512 threads.
// CTA (n,c) owns COLUMN quarter c of D (and L-quarter c of att): it reads
// only g_g[n][c*256:(c+1)*256] + its private z replica g_z4[n][c], zeroes
// exactly what it read (race-free), then streams evict-first stores.
// ---------------------------------------------------------------------------
__global__ void __launch_bounds__(512) pass2_kernel(
    float* __restrict__ fhat, float* __restrict__ att)
{
    __shared__ float4 gsh[64];                    // 1 KB: normalized D-quarter
    __shared__ __align__(16) float esh[128];      // 512 B: normalized L-quarter

    int n = blockIdx.x, c = blockIdx.y;
    int tid = threadIdx.x;

    float inv = __frcp_rn(g_z4[n][0] );
    // NOTE: all replicas hold the same total; use own replica for cleanup
    inv = __frcp_rn(g_z4[n][c]);

    if (tid < 64) {
        float4 g = reinterpret_cast<const float4*>(&g_g[n][0])[c * 64 + tid];
        g.x *= inv; g.y *= inv; g.z *= inv; g.w *= inv;
        gsh[tid] = g;
        // self-clean for next launch/replay
        reinterpret_cast<float4*>(&g_g[n][0])[c * 64 + tid] =
            make_float4(0.f, 0.f, 0.f, 0.f);
    } else if (tid < 192) {
        int l = c * 128 + (tid - 64);
        esh[tid - 64] = g_e[n][l] * inv;          // g_e overwritten each run: no clean
    } else if (tid == 192) {
        g_z4[n][c] = 0.f;                         // clean own replica
    }
    __syncthreads();

    // att[n, t, c*128 : c*128+128] for all t: 128 rows x 32 float4 = 4096 f4
    {
        const float4* es4 = reinterpret_cast<const float4*>(esh);
        float* abase = att + (size_t)n * T_ * L_ + c * 128;
#pragma unroll
        for (int k = tid; k < T_ * 32; k += 512) {
            int t = k >> 5, f = k & 31;
            __stcs(reinterpret_cast<float4*>(abase + (size_t)t * L_) + f, es4[f]);
        }
    }

    // fhat[n, t, c*256 : c*256+256] for all t: 128 rows x 64 float4 = 8192 f4
    {
        float4* obase = reinterpret_cast<float4*>(fhat)
                        + (size_t)n * T_ * D4 + c * 64;
#pragma unroll
        for (int k = tid; k < T_ * 64; k += 512) {
            int t = k >> 6, f = k & 63;
            __stcs(obase + (size_t)t * D4 + f, gsh[f]);
        }
    }
}

// ---------------------------------------------------------------------------
extern "C" void kernel_launch(void* const* d_in, const int* in_sizes, int n_in,
                              void* d_out, int out_size)
{
    const float* f1 = (const float*)d_in[0];  // [N,L,D]
    // d_in[1] = feature_2 : unused (softmax shift-invariance cancels it)
    const float* w  = (const float*)d_in[2];  // [D]
    // d_in[3] = b : unused (cancels in softmax)

    float* fhat = (float*)d_out;                         // [N,T,D]
    float* att  = (float*)d_out + (size_t)N_ * T_ * D_;  // [N,T,L]

    pass1_kernel<<< dim3(NTILES, N_), 256 >>> (f1, w);
    pass2_kernel<<< dim3(N_, 4), 512 >>> (fhat, att);
}